// round 3
// baseline (speedup 1.0000x reference)
#include <cuda_runtime.h>
#include <cuda_bf16.h>
#include <math.h>
#include <stdint.h>

#define TT 512
#define BB 64
#define II 1024
#define HH 1024
#define G4 4096

// ---------------- device scratch (static, no runtime alloc) ----------------
static __device__ float g_gx[(size_t)TT * BB * G4];        // 512MB fp32: gx + bx + bh
static __device__ float g_c[BB * HH];                      // cell state
// Fragment-layout bf16 blobs, [split: 0=hi, 1=lo]
static __device__ uint32_t g_whfrag[2][256 * 64 * 32 * 4]; // Wh: [mt256][kt64][lane32][reg4]
static __device__ uint32_t g_wxfrag[2][512 * 64 * 32 * 2]; // Wx: [nt512][kt64][lane32][reg2]
static __device__ uint32_t g_xfrag[2][(size_t)2048 * 64 * 32 * 4]; // X: [mt2048][kt][lane][reg4]
static __device__ uint32_t g_hfrag[2][2][64 * 8 * 32 * 2]; // h: [buf][split][kt64][nt8][lane][reg2]

// ---------------- mma.sync m16n8k16 bf16 (base sm_80+ instruction) ---------
__device__ __forceinline__ void mma16816(float* c, const uint32_t* a, const uint32_t* b) {
    asm volatile(
        "mma.sync.aligned.m16n8k16.row.col.f32.bf16.bf16.f32 "
        "{%0,%1,%2,%3}, {%4,%5,%6,%7}, {%8,%9}, {%0,%1,%2,%3};"
        : "+f"(c[0]), "+f"(c[1]), "+f"(c[2]), "+f"(c[3])
        : "r"(a[0]), "r"(a[1]), "r"(a[2]), "r"(a[3]), "r"(b[0]), "r"(b[1]));
}

__device__ __forceinline__ void split2(float w, __nv_bfloat16& hi, __nv_bfloat16& lo) {
    hi = __float2bfloat16(w);
    lo = __float2bfloat16(w - __bfloat162float(hi));
}

// ---------------------------------------------------------------------------
// Pack kernels: build fragment-order bf16 hi/lo blobs.
// A-fragment (16x16): lane=((r&7)<<2)|((kk>>1)&3), reg=((kk>>3)<<1)|(r>>3), half=kk&1
// B-fragment (16x8):  lane=((n&7)<<2)|((kk>>1)&3), reg=kk>>3,              half=kk&1
// ---------------------------------------------------------------------------
__global__ __launch_bounds__(256) void pack_wh(const float* __restrict__ Wh) {
    int idx = blockIdx.x * 256 + threadIdx.x;   // 4096*1024
    int row = idx >> 10, k = idx & 1023;
    int g = row >> 10, u = row & 1023;
    int ct = u >> 4, ul = u & 15;
    int mt = ct * 4 + g;
    int kt = k >> 4, kk = k & 15;
    int lane = ((ul & 7) << 2) | ((kk >> 1) & 3);
    int reg = ((kk >> 3) << 1) | (ul >> 3);
    int half = kk & 1;
    size_t wi = ((size_t)(mt * 64 + kt) * 32 + lane) * 4 + reg;
    __nv_bfloat16 hi, lo;
    split2(Wh[idx], hi, lo);
    ((__nv_bfloat16*)&g_whfrag[0][wi])[half] = hi;
    ((__nv_bfloat16*)&g_whfrag[1][wi])[half] = lo;
}

__global__ __launch_bounds__(256) void pack_wx(const float* __restrict__ Wx) {
    int idx = blockIdx.x * 256 + threadIdx.x;   // 4096*1024
    int n = idx >> 10, k = idx & 1023;
    int nt = n >> 3, nl = n & 7;
    int kt = k >> 4, kk = k & 15;
    int lane = (nl << 2) | ((kk >> 1) & 3);
    int reg = kk >> 3;
    int half = kk & 1;
    size_t wi = ((size_t)(nt * 64 + kt) * 32 + lane) * 2 + reg;
    __nv_bfloat16 hi, lo;
    split2(Wx[idx], hi, lo);
    ((__nv_bfloat16*)&g_wxfrag[0][wi])[half] = hi;
    ((__nv_bfloat16*)&g_wxfrag[1][wi])[half] = lo;
}

__global__ __launch_bounds__(256) void pack_x(const float* __restrict__ X) {
    size_t idx = (size_t)blockIdx.x * 256 + threadIdx.x;  // 32768*1024
    int row = (int)(idx >> 10), k = (int)(idx & 1023);
    int mt = row >> 4, r = row & 15;
    int kt = k >> 4, kk = k & 15;
    int lane = ((r & 7) << 2) | ((kk >> 1) & 3);
    int reg = ((kk >> 3) << 1) | (r >> 3);
    int half = kk & 1;
    size_t wi = (((size_t)mt * 64 + kt) * 32 + lane) * 4 + reg;
    __nv_bfloat16 hi, lo;
    split2(X[idx], hi, lo);
    ((__nv_bfloat16*)&g_xfrag[0][wi])[half] = hi;
    ((__nv_bfloat16*)&g_xfrag[1][wi])[half] = lo;
}

__global__ __launch_bounds__(256) void pack_h0(const float* __restrict__ h0) {
    int idx = blockIdx.x * 256 + threadIdx.x;   // 64*1024
    int b = idx >> 10, u = idx & 1023;
    int kt = u >> 4, kk = u & 15;
    int nt = b >> 3;
    int lane = ((b & 7) << 2) | ((kk >> 1) & 3);
    int reg = kk >> 3;
    int half = kk & 1;
    size_t wi = ((size_t)(kt * 8 + nt) * 32 + lane) * 2 + reg;
    __nv_bfloat16 hi, lo;
    split2(h0[idx], hi, lo);
    ((__nv_bfloat16*)&g_hfrag[0][0][wi])[half] = hi;
    ((__nv_bfloat16*)&g_hfrag[0][1][wi])[half] = lo;
}

// ---------------------------------------------------------------------------
// gx GEMM (tensor): gx[m,n] = X[m,:]·Wx[n,:] + bx[n] + bh[n]
// grid (32, 256): x = n-block (128 cols), y = m-block (128 rows). 8 warps:
// warp (wm=wid&1, wn=wid>>1): 4 mtiles x 4 ntiles (64x32 C tile).
// ---------------------------------------------------------------------------
__global__ __launch_bounds__(256) void gx_mma_kernel(
    const float* __restrict__ bx, const float* __restrict__ bh)
{
    const int tid = threadIdx.x;
    const int wid = tid >> 5, lane = tid & 31;
    const int wm = wid & 1, wn = wid >> 1;
    const int mtb = blockIdx.y * 8 + wm * 4;
    const int ntb = blockIdx.x * 16 + wn * 4;

    float acc[4][4][4];
#pragma unroll
    for (int i = 0; i < 4; i++)
#pragma unroll
        for (int j = 0; j < 4; j++)
#pragma unroll
            for (int q = 0; q < 4; q++) acc[i][j][q] = 0.f;

    const uint32_t* Ah = g_xfrag[0] + (size_t)lane * 4;
    const uint32_t* Al = g_xfrag[1] + (size_t)lane * 4;
    const uint32_t* Bh = g_wxfrag[0] + (size_t)lane * 2;
    const uint32_t* Bl = g_wxfrag[1] + (size_t)lane * 2;

#pragma unroll 2
    for (int kt = 0; kt < 64; kt++) {
        uint32_t b_h[4][2], b_l[4][2];
#pragma unroll
        for (int nt = 0; nt < 4; nt++) {
            size_t bo = (size_t)((ntb + nt) * 64 + kt) * 64;
            *(uint2*)b_h[nt] = *(const uint2*)(Bh + bo);
            *(uint2*)b_l[nt] = *(const uint2*)(Bl + bo);
        }
#pragma unroll
        for (int mt = 0; mt < 4; mt++) {
            size_t ao = ((size_t)(mtb + mt) * 64 + kt) * 128;
            uint32_t a_h[4], a_l[4];
            *(uint4*)a_h = *(const uint4*)(Ah + ao);
            *(uint4*)a_l = *(const uint4*)(Al + ao);
#pragma unroll
            for (int nt = 0; nt < 4; nt++) {
                mma16816(acc[mt][nt], a_h, b_h[nt]);
                mma16816(acc[mt][nt], a_l, b_h[nt]);
                mma16816(acc[mt][nt], a_h, b_l[nt]);
            }
        }
    }

    // epilogue: add biases, write fp32
#pragma unroll
    for (int mt = 0; mt < 4; mt++) {
        int row = (mtb + mt) * 16 + (lane >> 2);
#pragma unroll
        for (int nt = 0; nt < 4; nt++) {
            int col = (ntb + nt) * 8 + (lane & 3) * 2;
            float bb0 = bx[col] + bh[col];
            float bb1 = bx[col + 1] + bh[col + 1];
            float2 v0 = make_float2(acc[mt][nt][0] + bb0, acc[mt][nt][1] + bb1);
            float2 v1 = make_float2(acc[mt][nt][2] + bb0, acc[mt][nt][3] + bb1);
            *(float2*)(g_gx + (size_t)row * G4 + col) = v0;
            *(float2*)(g_gx + (size_t)(row + 8) * G4 + col) = v1;
        }
    }
}

// ---------------------------------------------------------------------------
// Recurrent step (tensor): 64 CTAs x 128 threads.
// CTA ct owns units [ct*16, ct*16+16); warp g computes gate g: M=16, N=64.
// K=1024: 64 ktiles, 8 ntiles, 3 split products -> 1536 HMMA/warp.
// ---------------------------------------------------------------------------
__global__ __launch_bounds__(128) void lstm_step_mma(
    const float* __restrict__ c0,
    float* __restrict__ out,
    float* __restrict__ hfin, float* __restrict__ cfin,
    int t, int last_full)
{
    __shared__ float Gs[4][16][66];

    const int tid = threadIdx.x;
    const int wid = tid >> 5, lane = tid & 31;
    const int ct = blockIdx.x;

    const uint32_t* Ah = g_whfrag[0] + ((size_t)(ct * 4 + wid) * 64) * 128 + lane * 4;
    const uint32_t* Al = g_whfrag[1] + ((size_t)(ct * 4 + wid) * 64) * 128 + lane * 4;
    const uint32_t* Bh = g_hfrag[t & 1][0] + lane * 2;
    const uint32_t* Bl = g_hfrag[t & 1][1] + lane * 2;

    float acc[8][4];
#pragma unroll
    for (int i = 0; i < 8; i++)
#pragma unroll
        for (int q = 0; q < 4; q++) acc[i][q] = 0.f;

#pragma unroll 4
    for (int kt = 0; kt < 64; kt++) {
        uint32_t a_h[4], a_l[4];
        *(uint4*)a_h = *(const uint4*)(Ah + (size_t)kt * 128);
        *(uint4*)a_l = *(const uint4*)(Al + (size_t)kt * 128);
#pragma unroll
        for (int nt = 0; nt < 8; nt++) {
            uint32_t b_h[2], b_l[2];
            size_t bo = (size_t)(kt * 8 + nt) * 64;
            *(uint2*)b_h = *(const uint2*)(Bh + bo);
            *(uint2*)b_l = *(const uint2*)(Bl + bo);
            mma16816(acc[nt], a_h, b_h);
            mma16816(acc[nt], a_l, b_h);
            mma16816(acc[nt], a_h, b_l);
        }
    }

    // scatter C fragments to smem: Gs[gate][unit_local][batch]
#pragma unroll
    for (int nt = 0; nt < 8; nt++) {
        int b = nt * 8 + (lane & 3) * 2;
        int ul = lane >> 2;
        Gs[wid][ul][b] = acc[nt][0];
        Gs[wid][ul][b + 1] = acc[nt][1];
        Gs[wid][ul + 8][b] = acc[nt][2];
        Gs[wid][ul + 8][b + 1] = acc[nt][3];
    }
    __syncthreads();

    // fused cell update: thread (ul = tid&15, bg = tid>>4) handles 8 batches
    const int ul = tid & 15;
    const int bg = tid >> 4;
    const int u = ct * 16 + ul;
    const float* cin = (t == 0) ? c0 : g_c;
    float* outt = out + (size_t)t * BB * HH;
    uint32_t* hoH = g_hfrag[(t + 1) & 1][0];
    uint32_t* hoL = g_hfrag[(t + 1) & 1][1];

#pragma unroll
    for (int i = 0; i < 8; i++) {
        const int b = bg * 8 + i;
        const float* gxr = g_gx + ((size_t)t * BB + b) * G4;
        float xi = Gs[0][ul][b] + gxr[u];
        float xf = Gs[1][ul][b] + gxr[HH + u];
        float xo = Gs[2][ul][b] + gxr[2 * HH + u];
        float xn = Gs[3][ul][b] + gxr[3 * HH + u];

        float ig = 1.f / (1.f + __expf(-xi));
        float fg = 1.f / (1.f + __expf(-xf));
        float og = 1.f / (1.f + __expf(-xo));
        float ng = tanhf(xn);

        float cprev = cin[(size_t)b * HH + u];
        float cnew = fg * cprev + ig * ng;
        float hnew = og * tanhf(cnew);

        g_c[(size_t)b * HH + u] = cnew;
        outt[(size_t)b * HH + u] = hnew;

        // next-step B fragment: kt = ct, kk = ul
        int nt = b >> 3;
        int lane_t = ((b & 7) << 2) | ((ul >> 1) & 3);
        int reg = ul >> 3;
        int half = ul & 1;
        size_t wi = ((size_t)(ct * 8 + nt) * 32 + lane_t) * 2 + reg;
        __nv_bfloat16 hh, hl;
        split2(hnew, hh, hl);
        ((__nv_bfloat16*)&hoH[wi])[half] = hh;
        ((__nv_bfloat16*)&hoL[wi])[half] = hl;

        if (last_full) {
            hfin[(size_t)b * HH + u] = hnew;
            cfin[(size_t)b * HH + u] = cnew;
        }
    }
}

// ---------------------------------------------------------------------------
extern "C" void kernel_launch(void* const* d_in, const int* in_sizes, int n_in,
                              void* d_out, int out_size)
{
    const float* input_ = (const float*)d_in[0];
    const float* h0     = (const float*)d_in[1];
    const float* c0     = (const float*)d_in[2];
    const float* Wx     = (const float*)d_in[3];
    const float* Wh     = (const float*)d_in[4];
    const float* bx     = (const float*)d_in[5];
    const float* bh     = (const float*)d_in[6];
    float* out = (float*)d_out;
    (void)in_sizes; (void)n_in;

    // prep: pack operands into fragment-layout bf16 hi/lo blobs
    pack_wh<<<(G4 * HH) / 256, 256>>>(Wh);
    pack_wx<<<(G4 * II) / 256, 256>>>(Wx);
    pack_x<<<(int)(((size_t)TT * BB * II) / 256), 256>>>(input_);
    pack_h0<<<(BB * HH) / 256, 256>>>(h0);

    // gx = X @ Wx^T + bx + bh  (tensor)
    dim3 ggrid(G4 / 128, (TT * BB) / 128);
    gx_mma_kernel<<<ggrid, 256>>>(bx, bh);

    long long need = (long long)TT * BB * HH + 2LL * BB * HH;
    int full = (out_size >= need) ? 1 : 0;
    float* hfin = out + (size_t)TT * BB * HH;
    float* cfin = hfin + (size_t)BB * HH;

    for (int t = 0; t < TT; t++) {
        int lastf = (t == TT - 1) ? full : 0;
        lstm_step_mma<<<64, 128>>>(c0, out, hfin, cfin, t, lastf);
    }
}

// round 4
// speedup vs baseline: 3.5275x; 3.5275x over previous
#include <cuda_runtime.h>
#include <cuda_bf16.h>
#include <math.h>
#include <stdint.h>

#define TT 512
#define BB 64
#define II 1024
#define HH 1024
#define G4 4096
#define NCTA 128

// ---------------- device scratch (static, no runtime alloc) ----------------
static __device__ float g_gx[(size_t)TT * BB * G4];        // fp32: X@Wx^T + bx + bh
// Wh fragments, per-CTA contiguous blob: [c128][s2][mt2][kt64][lane32][reg4]
static __device__ uint32_t g_whp[(size_t)NCTA * 32768];
static __device__ uint32_t g_wxfrag[2][512 * 64 * 32 * 2]; // Wx: [nt512][kt64][lane32][reg2]
static __device__ uint32_t g_xfrag[2][(size_t)2048 * 64 * 32 * 4]; // X frags
static __device__ uint32_t g_hfrag[2][2][64 * 8 * 32 * 2]; // h: [buf][split][kt][nt][lane][reg]
static __device__ int g_arrive;
static __device__ int g_gen;

// ---------------- mma.sync m16n8k16 bf16 ----------------
__device__ __forceinline__ void mma16816(float* c, const uint32_t* a, const uint32_t* b) {
    asm volatile(
        "mma.sync.aligned.m16n8k16.row.col.f32.bf16.bf16.f32 "
        "{%0,%1,%2,%3}, {%4,%5,%6,%7}, {%8,%9}, {%0,%1,%2,%3};"
        : "+f"(c[0]), "+f"(c[1]), "+f"(c[2]), "+f"(c[3])
        : "r"(a[0]), "r"(a[1]), "r"(a[2]), "r"(a[3]), "r"(b[0]), "r"(b[1]));
}

__device__ __forceinline__ void split2(float w, __nv_bfloat16& hi, __nv_bfloat16& lo) {
    hi = __float2bfloat16(w);
    lo = __float2bfloat16(w - __bfloat162float(hi));
}

// ---------------------------------------------------------------------------
// Pack kernels (fragment layouts empirically validated in Round 3).
// ---------------------------------------------------------------------------
__global__ __launch_bounds__(256) void pack_whp(const float* __restrict__ Wh) {
    int idx = blockIdx.x * 256 + threadIdx.x;   // 4096*1024
    int row = idx >> 10, k = idx & 1023;
    int g = row >> 10, u = row & 1023;
    int c = u >> 3, ul = u & 7;
    int rm = g * 8 + ul;                        // row within CTA's 32
    int mt = rm >> 4, r = rm & 15;
    int kt = k >> 4, kk = k & 15;
    int lane = ((r & 7) << 2) | ((kk >> 1) & 3);
    int reg = ((kk >> 3) << 1) | (r >> 3);
    int half = kk & 1;
    size_t base = (size_t)c * 32768 + ((size_t)mt * 64 + kt) * 128 + lane * 4 + reg;
    __nv_bfloat16 hi, lo;
    split2(Wh[idx], hi, lo);
    ((__nv_bfloat16*)&g_whp[base])[half] = hi;
    ((__nv_bfloat16*)&g_whp[base + 16384])[half] = lo;
}

__global__ __launch_bounds__(256) void pack_wx(const float* __restrict__ Wx) {
    int idx = blockIdx.x * 256 + threadIdx.x;   // 4096*1024
    int n = idx >> 10, k = idx & 1023;
    int nt = n >> 3, nl = n & 7;
    int kt = k >> 4, kk = k & 15;
    int lane = (nl << 2) | ((kk >> 1) & 3);
    int reg = kk >> 3;
    int half = kk & 1;
    size_t wi = ((size_t)(nt * 64 + kt) * 32 + lane) * 2 + reg;
    __nv_bfloat16 hi, lo;
    split2(Wx[idx], hi, lo);
    ((__nv_bfloat16*)&g_wxfrag[0][wi])[half] = hi;
    ((__nv_bfloat16*)&g_wxfrag[1][wi])[half] = lo;
}

__global__ __launch_bounds__(256) void pack_x(const float* __restrict__ X) {
    size_t idx = (size_t)blockIdx.x * 256 + threadIdx.x;  // 32768*1024
    int row = (int)(idx >> 10), k = (int)(idx & 1023);
    int mt = row >> 4, r = row & 15;
    int kt = k >> 4, kk = k & 15;
    int lane = ((r & 7) << 2) | ((kk >> 1) & 3);
    int reg = ((kk >> 3) << 1) | (r >> 3);
    int half = kk & 1;
    size_t wi = (((size_t)mt * 64 + kt) * 32 + lane) * 4 + reg;
    __nv_bfloat16 hi, lo;
    split2(X[idx], hi, lo);
    ((__nv_bfloat16*)&g_xfrag[0][wi])[half] = hi;
    ((__nv_bfloat16*)&g_xfrag[1][wi])[half] = lo;
}

__global__ __launch_bounds__(256) void pack_h0(const float* __restrict__ h0) {
    int idx = blockIdx.x * 256 + threadIdx.x;   // 64*1024
    int b = idx >> 10, u = idx & 1023;
    int kt = u >> 4, kk = u & 15;
    int nt = b >> 3;
    int lane = ((b & 7) << 2) | ((kk >> 1) & 3);
    int reg = kk >> 3;
    int half = kk & 1;
    size_t wi = ((size_t)(kt * 8 + nt) * 32 + lane) * 2 + reg;
    __nv_bfloat16 hi, lo;
    split2(h0[idx], hi, lo);
    ((__nv_bfloat16*)&g_hfrag[0][0][wi])[half] = hi;
    ((__nv_bfloat16*)&g_hfrag[0][1][wi])[half] = lo;
}

__global__ void reset_bar() { g_arrive = 0; g_gen = 0; }

// ---------------------------------------------------------------------------
// gx GEMM (tensor, unchanged from R3): gx = X@Wx^T + bx + bh
// ---------------------------------------------------------------------------
__global__ __launch_bounds__(256) void gx_mma_kernel(
    const float* __restrict__ bx, const float* __restrict__ bh)
{
    const int tid = threadIdx.x;
    const int wid = tid >> 5, lane = tid & 31;
    const int wm = wid & 1, wn = wid >> 1;
    const int mtb = blockIdx.y * 8 + wm * 4;
    const int ntb = blockIdx.x * 16 + wn * 4;

    float acc[4][4][4];
#pragma unroll
    for (int i = 0; i < 4; i++)
#pragma unroll
        for (int j = 0; j < 4; j++)
#pragma unroll
            for (int q = 0; q < 4; q++) acc[i][j][q] = 0.f;

    const uint32_t* Ah = g_xfrag[0] + (size_t)lane * 4;
    const uint32_t* Al = g_xfrag[1] + (size_t)lane * 4;
    const uint32_t* Bh = g_wxfrag[0] + (size_t)lane * 2;
    const uint32_t* Bl = g_wxfrag[1] + (size_t)lane * 2;

#pragma unroll 2
    for (int kt = 0; kt < 64; kt++) {
        uint32_t b_h[4][2], b_l[4][2];
#pragma unroll
        for (int nt = 0; nt < 4; nt++) {
            size_t bo = (size_t)((ntb + nt) * 64 + kt) * 64;
            *(uint2*)b_h[nt] = *(const uint2*)(Bh + bo);
            *(uint2*)b_l[nt] = *(const uint2*)(Bl + bo);
        }
#pragma unroll
        for (int mt = 0; mt < 4; mt++) {
            size_t ao = ((size_t)(mtb + mt) * 64 + kt) * 128;
            uint32_t a_h[4], a_l[4];
            *(uint4*)a_h = *(const uint4*)(Ah + ao);
            *(uint4*)a_l = *(const uint4*)(Al + ao);
#pragma unroll
            for (int nt = 0; nt < 4; nt++) {
                mma16816(acc[mt][nt], a_h, b_h[nt]);
                mma16816(acc[mt][nt], a_l, b_h[nt]);
                mma16816(acc[mt][nt], a_h, b_l[nt]);
            }
        }
    }

#pragma unroll
    for (int mt = 0; mt < 4; mt++) {
        int row = (mtb + mt) * 16 + (lane >> 2);
#pragma unroll
        for (int nt = 0; nt < 4; nt++) {
            int col = (ntb + nt) * 8 + (lane & 3) * 2;
            float bb0 = bx[col] + bh[col];
            float bb1 = bx[col + 1] + bh[col + 1];
            float2 v0 = make_float2(acc[mt][nt][0] + bb0, acc[mt][nt][1] + bb1);
            float2 v1 = make_float2(acc[mt][nt][2] + bb0, acc[mt][nt][3] + bb1);
            *(float2*)(g_gx + (size_t)row * G4 + col) = v0;
            *(float2*)(g_gx + (size_t)(row + 8) * G4 + col) = v1;
        }
    }
}

// ---------------------------------------------------------------------------
// Persistent recurrence kernel: 128 CTAs x 256 threads, 512 steps in one launch.
// CTA c owns cells [c*8, c*8+8) (32 gate rows). Warp w: mt = w>>2, q = w&3.
// Wh fragments resident in SMEM; grid barrier per step via global atomics.
// SMEM: whs 128KB | Gs 4x32x68 f32 | cs 512 f32
// ---------------------------------------------------------------------------
#define GS_OFF   131072
#define CS_OFF   (131072 + 4 * 32 * 68 * 4)
#define SM_TOTAL (CS_OFF + 2048)

__global__ __launch_bounds__(256, 1) void lstm_persist(
    const float* __restrict__ c0,
    float* __restrict__ out,
    float* __restrict__ hfin, float* __restrict__ cfin,
    int full)
{
    extern __shared__ __align__(16) char sm[];
    uint32_t (*whs)[2][64][128] = (uint32_t (*)[2][64][128])sm;
    float (*Gs)[32][68] = (float (*)[32][68])(sm + GS_OFF);
    float* cs = (float*)(sm + CS_OFF);

    const int cta = blockIdx.x;
    const int tid = threadIdx.x;
    const int wid = tid >> 5, lane = tid & 31;
    const int mt = wid >> 2, q = wid & 3;

    // load Wh fragment slice (once) and cell state
    {
        const uint4* src = (const uint4*)(g_whp + (size_t)cta * 32768);
        uint4* dst = (uint4*)sm;
        for (int i = tid; i < 8192; i += 256) dst[i] = src[i];
        for (int i = tid; i < 512; i += 256) {
            int b = i >> 3, ul = i & 7;
            cs[i] = c0[(size_t)b * HH + cta * 8 + ul];
        }
    }
    __syncthreads();

    for (int t = 0; t < TT; t++) {
        const uint32_t* Bh = &g_hfrag[t & 1][0][0];
        const uint32_t* Bl = &g_hfrag[t & 1][1][0];

        float acc[8][4];
#pragma unroll
        for (int i = 0; i < 8; i++)
#pragma unroll
            for (int j = 0; j < 4; j++) acc[i][j] = 0.f;

        const int kt0 = q * 16;
#pragma unroll 2
        for (int kt = kt0; kt < kt0 + 16; kt++) {
            uint4 a_hv = *(const uint4*)&whs[0][mt][kt][lane * 4];
            uint4 a_lv = *(const uint4*)&whs[1][mt][kt][lane * 4];
            const uint32_t* a_h = (const uint32_t*)&a_hv;
            const uint32_t* a_l = (const uint32_t*)&a_lv;
            uint2 bh[8], bl[8];
#pragma unroll
            for (int nt = 0; nt < 8; nt++) {
                uint32_t off = (uint32_t)(kt * 8 + nt) * 64 + lane * 2;
                bh[nt] = __ldcg((const uint2*)(Bh + off));
                bl[nt] = __ldcg((const uint2*)(Bl + off));
            }
#pragma unroll
            for (int nt = 0; nt < 8; nt++) mma16816(acc[nt], a_h, (const uint32_t*)&bh[nt]);
#pragma unroll
            for (int nt = 0; nt < 8; nt++) mma16816(acc[nt], a_l, (const uint32_t*)&bh[nt]);
#pragma unroll
            for (int nt = 0; nt < 8; nt++) mma16816(acc[nt], a_h, (const uint32_t*)&bl[nt]);
        }

        // scatter partials: Gs[q][row32][b]
        {
            const int r0 = mt * 16 + (lane >> 2);
#pragma unroll
            for (int nt = 0; nt < 8; nt++) {
                int col = nt * 8 + (lane & 3) * 2;
                Gs[q][r0][col]     = acc[nt][0];
                Gs[q][r0][col + 1] = acc[nt][1];
                Gs[q][r0 + 8][col]     = acc[nt][2];
                Gs[q][r0 + 8][col + 1] = acc[nt][3];
            }
        }
        __syncthreads();

        // cell update: 2 cells per thread
        float* outt = out + (size_t)t * BB * HH;
        const int nb = (t + 1) & 1;
#pragma unroll
        for (int pp = 0; pp < 2; pp++) {
            const int p = tid + pp * 256;
            const int b = p >> 3, ul = p & 7;
            const int u = cta * 8 + ul;
            const float* gxr = g_gx + ((size_t)t * BB + b) * G4 + u;

            float x0 = Gs[0][ul][b] + Gs[1][ul][b] + Gs[2][ul][b] + Gs[3][ul][b]
                       + __ldcg(gxr);
            float x1 = Gs[0][8 + ul][b] + Gs[1][8 + ul][b] + Gs[2][8 + ul][b] + Gs[3][8 + ul][b]
                       + __ldcg(gxr + HH);
            float x2 = Gs[0][16 + ul][b] + Gs[1][16 + ul][b] + Gs[2][16 + ul][b] + Gs[3][16 + ul][b]
                       + __ldcg(gxr + 2 * HH);
            float x3 = Gs[0][24 + ul][b] + Gs[1][24 + ul][b] + Gs[2][24 + ul][b] + Gs[3][24 + ul][b]
                       + __ldcg(gxr + 3 * HH);

            float ig = 1.f / (1.f + __expf(-x0));
            float fg = 1.f / (1.f + __expf(-x1));
            float og = 1.f / (1.f + __expf(-x2));
            float ng = tanhf(x3);

            float cprev = cs[p];
            float cnew = fg * cprev + ig * ng;
            float hnew = og * tanhf(cnew);
            cs[p] = cnew;
            outt[(size_t)b * HH + u] = hnew;

            // next-step B fragment write
            int kt = u >> 4, kk = u & 15, nt = b >> 3;
            int lt = ((b & 7) << 2) | ((kk >> 1) & 3);
            int rg = kk >> 3, hf = kk & 1;
            size_t wi = ((size_t)(kt * 8 + nt) * 32 + lt) * 2 + rg;
            __nv_bfloat16 hh, hl;
            split2(hnew, hh, hl);
            ((__nv_bfloat16*)&g_hfrag[nb][0][wi])[hf] = hh;
            ((__nv_bfloat16*)&g_hfrag[nb][1][wi])[hf] = hl;

            if (t == TT - 1 && full) {
                hfin[(size_t)b * HH + u] = hnew;
                cfin[(size_t)b * HH + u] = cnew;
            }
        }

        // grid barrier
        __threadfence();
        __syncthreads();
        if (tid == 0) {
            int v = atomicAdd(&g_arrive, 1);
            if (v == NCTA * (t + 1) - 1) atomicExch(&g_gen, t + 1);
            volatile int* vg = &g_gen;
            while (*vg < t + 1) __nanosleep(64);
        }
        __syncthreads();
    }
}

// ---------------------------------------------------------------------------
extern "C" void kernel_launch(void* const* d_in, const int* in_sizes, int n_in,
                              void* d_out, int out_size)
{
    const float* input_ = (const float*)d_in[0];
    const float* h0     = (const float*)d_in[1];
    const float* c0     = (const float*)d_in[2];
    const float* Wx     = (const float*)d_in[3];
    const float* Wh     = (const float*)d_in[4];
    const float* bx     = (const float*)d_in[5];
    const float* bh     = (const float*)d_in[6];
    float* out = (float*)d_out;
    (void)in_sizes; (void)n_in;

    cudaFuncSetAttribute(lstm_persist, cudaFuncAttributeMaxDynamicSharedMemorySize, SM_TOTAL);

    reset_bar<<<1, 1>>>();
    pack_whp<<<(G4 * HH) / 256, 256>>>(Wh);
    pack_wx<<<(G4 * II) / 256, 256>>>(Wx);
    pack_x<<<(int)(((size_t)TT * BB * II) / 256), 256>>>(input_);
    pack_h0<<<(BB * HH) / 256, 256>>>(h0);

    dim3 ggrid(G4 / 128, (TT * BB) / 128);
    gx_mma_kernel<<<ggrid, 256>>>(bx, bh);

    long long need = (long long)TT * BB * HH + 2LL * BB * HH;
    int full = (out_size >= need) ? 1 : 0;
    float* hfin = out + (size_t)TT * BB * HH;
    float* cfin = hfin + (size_t)BB * HH;

    lstm_persist<<<NCTA, 256, SM_TOTAL>>>(c0, out, hfin, cfin, full);
}

// round 5
// speedup vs baseline: 6.7834x; 1.9230x over previous
#include <cuda_runtime.h>
#include <cuda_fp16.h>
#include <math.h>
#include <stdint.h>

#define TT 512
#define BB 64
#define II 1024
#define HH 1024
#define G4 4096
#define NCTA 128

// ---------------- device scratch (static, no runtime alloc) ----------------
static __device__ float g_gx[(size_t)TT * BB * G4];        // fp32: X@Wx^T + bx + bh
// Wh fp16 weight-split, per-CTA blob: [c128][split2][mt2][kt64][lane32][reg4]
static __device__ uint32_t g_whp[(size_t)NCTA * 32768];
// Wx fp16 weight-split: [split2][nt512][kt64][lane32][reg2]
static __device__ uint32_t g_wxfrag[2][(size_t)512 * 64 * 64];
// X single fp16: [mt2048][kt64][lane32][reg4]
static __device__ uint32_t g_xfrag[(size_t)2048 * 64 * 128];
// h single fp16 (double buffered): [buf2][kt64][nt8][lane32][reg2]
static __device__ uint32_t g_hfrag[2][64 * 8 * 64];
static __device__ int g_arrive;
static __device__ int g_gen;

// ---------------- mma.sync m16n8k16 fp16 (base sm_80+) ----------------
__device__ __forceinline__ void mma16816(float* c, const uint32_t* a, const uint32_t* b) {
    asm volatile(
        "mma.sync.aligned.m16n8k16.row.col.f32.f16.f16.f32 "
        "{%0,%1,%2,%3}, {%4,%5,%6,%7}, {%8,%9}, {%0,%1,%2,%3};"
        : "+f"(c[0]), "+f"(c[1]), "+f"(c[2]), "+f"(c[3])
        : "r"(a[0]), "r"(a[1]), "r"(a[2]), "r"(a[3]), "r"(b[0]), "r"(b[1]));
}

__device__ __forceinline__ void wsplit(float w, __half& hi, __half& lo) {
    hi = __float2half_rn(w);
    lo = __float2half_rn(w - __half2float(hi));
}

// ---------------------------------------------------------------------------
// Pack kernels. Fragment layouts (validated R3/R4):
// A (16x16): lane=((r&7)<<2)|((kk>>1)&3), reg=((kk>>3)<<1)|(r>>3), half=kk&1
// B (8x16):  lane=((n&7)<<2)|((kk>>1)&3), reg=kk>>3,               half=kk&1
// ---------------------------------------------------------------------------
__global__ __launch_bounds__(256) void pack_whp(const float* __restrict__ Wh) {
    int idx = blockIdx.x * 256 + threadIdx.x;   // 4096*1024
    int row = idx >> 10, k = idx & 1023;
    int g = row >> 10, u = row & 1023;
    int c = u >> 3, ul = u & 7;
    int rm = g * 8 + ul;
    int mt = rm >> 4, r = rm & 15;
    int kt = k >> 4, kk = k & 15;
    int lane = ((r & 7) << 2) | ((kk >> 1) & 3);
    int reg = ((kk >> 3) << 1) | (r >> 3);
    int half = kk & 1;
    size_t base = (size_t)c * 32768 + ((size_t)mt * 64 + kt) * 128 + lane * 4 + reg;
    __half hi, lo;
    wsplit(Wh[idx], hi, lo);
    ((__half*)&g_whp[base])[half] = hi;
    ((__half*)&g_whp[base + 16384])[half] = lo;
}

__global__ __launch_bounds__(256) void pack_wx(const float* __restrict__ Wx) {
    int idx = blockIdx.x * 256 + threadIdx.x;   // 4096*1024
    int n = idx >> 10, k = idx & 1023;
    int nt = n >> 3, nl = n & 7;
    int kt = k >> 4, kk = k & 15;
    int lane = (nl << 2) | ((kk >> 1) & 3);
    int reg = kk >> 3;
    int half = kk & 1;
    size_t wi = ((size_t)(nt * 64 + kt) * 32 + lane) * 2 + reg;
    __half hi, lo;
    wsplit(Wx[idx], hi, lo);
    ((__half*)&g_wxfrag[0][wi])[half] = hi;
    ((__half*)&g_wxfrag[1][wi])[half] = lo;
}

__global__ __launch_bounds__(256) void pack_x(const float* __restrict__ X) {
    size_t idx = (size_t)blockIdx.x * 256 + threadIdx.x;  // 32768*1024
    int row = (int)(idx >> 10), k = (int)(idx & 1023);
    int mt = row >> 4, r = row & 15;
    int kt = k >> 4, kk = k & 15;
    int lane = ((r & 7) << 2) | ((kk >> 1) & 3);
    int reg = ((kk >> 3) << 1) | (r >> 3);
    int half = kk & 1;
    size_t wi = (((size_t)mt * 64 + kt) * 32 + lane) * 4 + reg;
    ((__half*)&g_xfrag[wi])[half] = __float2half_rn(X[idx]);
}

__global__ __launch_bounds__(256) void pack_h0(const float* __restrict__ h0) {
    int idx = blockIdx.x * 256 + threadIdx.x;   // 64*1024
    int b = idx >> 10, u = idx & 1023;
    int kt = u >> 4, kk = u & 15;
    int nt = b >> 3;
    int lane = ((b & 7) << 2) | ((kk >> 1) & 3);
    int reg = kk >> 3;
    int half = kk & 1;
    size_t wi = ((size_t)(kt * 8 + nt) * 32 + lane) * 2 + reg;
    ((__half*)&g_hfrag[0][wi])[half] = __float2half_rn(h0[idx]);
}

__global__ void reset_bar() { g_arrive = 0; g_gen = 0; }

// ---------------------------------------------------------------------------
// gx GEMM (tensor): gx = X@Wx^T + bx + bh. A = X (fp16 single), B = Wx (hi/lo).
// grid (32, 256); 8 warps: 4 mtiles x 4 ntiles each; 32 MMA per kt per warp.
// ---------------------------------------------------------------------------
__global__ __launch_bounds__(256) void gx_mma_kernel(
    const float* __restrict__ bx, const float* __restrict__ bh)
{
    const int tid = threadIdx.x;
    const int wid = tid >> 5, lane = tid & 31;
    const int wm = wid & 1, wn = wid >> 1;
    const int mtb = blockIdx.y * 8 + wm * 4;
    const int ntb = blockIdx.x * 16 + wn * 4;

    float acc[4][4][4];
#pragma unroll
    for (int i = 0; i < 4; i++)
#pragma unroll
        for (int j = 0; j < 4; j++)
#pragma unroll
            for (int q = 0; q < 4; q++) acc[i][j][q] = 0.f;

    const uint32_t* Af = g_xfrag + (size_t)lane * 4;
    const uint32_t* Bh = g_wxfrag[0] + (size_t)lane * 2;
    const uint32_t* Bl = g_wxfrag[1] + (size_t)lane * 2;

#pragma unroll 2
    for (int kt = 0; kt < 64; kt++) {
        uint32_t b_h[4][2], b_l[4][2];
#pragma unroll
        for (int nt = 0; nt < 4; nt++) {
            size_t bo = (size_t)((ntb + nt) * 64 + kt) * 64;
            *(uint2*)b_h[nt] = *(const uint2*)(Bh + bo);
            *(uint2*)b_l[nt] = *(const uint2*)(Bl + bo);
        }
#pragma unroll
        for (int mt = 0; mt < 4; mt++) {
            size_t ao = ((size_t)(mtb + mt) * 64 + kt) * 128;
            uint32_t a[4];
            *(uint4*)a = *(const uint4*)(Af + ao);
#pragma unroll
            for (int nt = 0; nt < 4; nt++) {
                mma16816(acc[mt][nt], a, b_h[nt]);
                mma16816(acc[mt][nt], a, b_l[nt]);
            }
        }
    }

#pragma unroll
    for (int mt = 0; mt < 4; mt++) {
        int row = (mtb + mt) * 16 + (lane >> 2);
#pragma unroll
        for (int nt = 0; nt < 4; nt++) {
            int col = (ntb + nt) * 8 + (lane & 3) * 2;
            float bb0 = bx[col] + bh[col];
            float bb1 = bx[col + 1] + bh[col + 1];
            float2 v0 = make_float2(acc[mt][nt][0] + bb0, acc[mt][nt][1] + bb1);
            float2 v1 = make_float2(acc[mt][nt][2] + bb0, acc[mt][nt][3] + bb1);
            *(float2*)(g_gx + (size_t)row * G4 + col) = v0;
            *(float2*)(g_gx + (size_t)(row + 8) * G4 + col) = v1;
        }
    }
}

// ---------------------------------------------------------------------------
// Persistent recurrence: 128 CTAs x 256 threads, 512 steps in one launch.
// CTA c owns cells [c*8, c*8+8). Warp w: mt = w>>2, K-quarter q = w&3.
// Wh fp16 hi/lo resident in SMEM; h single fp16 frags via L2; grid barrier.
// ---------------------------------------------------------------------------
#define GS_OFF   131072
#define CS_OFF   (131072 + 4 * 32 * 68 * 4)
#define SM_TOTAL (CS_OFF + 2048)

__global__ __launch_bounds__(256, 1) void lstm_persist(
    const float* __restrict__ c0,
    float* __restrict__ out,
    float* __restrict__ hfin, float* __restrict__ cfin,
    int full)
{
    extern __shared__ __align__(16) char sm[];
    uint32_t (*whs)[2][64][128] = (uint32_t (*)[2][64][128])sm;
    float (*Gs)[32][68] = (float (*)[32][68])(sm + GS_OFF);
    float* cs = (float*)(sm + CS_OFF);

    const int cta = blockIdx.x;
    const int tid = threadIdx.x;
    const int wid = tid >> 5, lane = tid & 31;
    const int mt = wid >> 2, q = wid & 3;

    {
        const uint4* src = (const uint4*)(g_whp + (size_t)cta * 32768);
        uint4* dst = (uint4*)sm;
        for (int i = tid; i < 8192; i += 256) dst[i] = src[i];
        for (int i = tid; i < 512; i += 256) {
            int b = i >> 3, ul = i & 7;
            cs[i] = c0[(size_t)b * HH + cta * 8 + ul];
        }
    }
    __syncthreads();

    for (int t = 0; t < TT; t++) {
        const uint32_t* Bf = &g_hfrag[t & 1][0];

        // prefetch gx epilogue values early (hidden under MMA)
        float gpre[2][4];
        {
#pragma unroll
            for (int pp = 0; pp < 2; pp++) {
                const int p = tid + pp * 256;
                const int b = p >> 3, ul = p & 7;
                const float* gxr = g_gx + ((size_t)t * BB + b) * G4 + cta * 8 + ul;
#pragma unroll
                for (int g = 0; g < 4; g++) gpre[pp][g] = __ldcg(gxr + g * HH);
            }
        }

        float acc[8][4];
#pragma unroll
        for (int i = 0; i < 8; i++)
#pragma unroll
            for (int j = 0; j < 4; j++) acc[i][j] = 0.f;

        const int kt0 = q * 16;
#pragma unroll 4
        for (int kt = kt0; kt < kt0 + 16; kt++) {
            uint4 a_hv = *(const uint4*)&whs[0][mt][kt][lane * 4];
            uint4 a_lv = *(const uint4*)&whs[1][mt][kt][lane * 4];
            const uint32_t* a_h = (const uint32_t*)&a_hv;
            const uint32_t* a_l = (const uint32_t*)&a_lv;
            uint2 bf[8];
#pragma unroll
            for (int nt = 0; nt < 8; nt++) {
                uint32_t off = (uint32_t)(kt * 8 + nt) * 64 + lane * 2;
                bf[nt] = __ldcg((const uint2*)(Bf + off));
            }
#pragma unroll
            for (int nt = 0; nt < 8; nt++) mma16816(acc[nt], a_h, (const uint32_t*)&bf[nt]);
#pragma unroll
            for (int nt = 0; nt < 8; nt++) mma16816(acc[nt], a_l, (const uint32_t*)&bf[nt]);
        }

        // scatter partials: Gs[q][row32][b]
        {
            const int r0 = mt * 16 + (lane >> 2);
#pragma unroll
            for (int nt = 0; nt < 8; nt++) {
                int col = nt * 8 + (lane & 3) * 2;
                Gs[q][r0][col]     = acc[nt][0];
                Gs[q][r0][col + 1] = acc[nt][1];
                Gs[q][r0 + 8][col]     = acc[nt][2];
                Gs[q][r0 + 8][col + 1] = acc[nt][3];
            }
        }
        __syncthreads();

        // cell update: 2 cells per thread
        float* outt = out + (size_t)t * BB * HH;
        const int nb = (t + 1) & 1;
#pragma unroll
        for (int pp = 0; pp < 2; pp++) {
            const int p = tid + pp * 256;
            const int b = p >> 3, ul = p & 7;
            const int u = cta * 8 + ul;

            float x0 = Gs[0][ul][b] + Gs[1][ul][b] + Gs[2][ul][b] + Gs[3][ul][b] + gpre[pp][0];
            float x1 = Gs[0][8 + ul][b] + Gs[1][8 + ul][b] + Gs[2][8 + ul][b] + Gs[3][8 + ul][b] + gpre[pp][1];
            float x2 = Gs[0][16 + ul][b] + Gs[1][16 + ul][b] + Gs[2][16 + ul][b] + Gs[3][16 + ul][b] + gpre[pp][2];
            float x3 = Gs[0][24 + ul][b] + Gs[1][24 + ul][b] + Gs[2][24 + ul][b] + Gs[3][24 + ul][b] + gpre[pp][3];

            float ig = 1.f / (1.f + __expf(-x0));
            float fg = 1.f / (1.f + __expf(-x1));
            float og = 1.f / (1.f + __expf(-x2));
            float ng = tanhf(x3);

            float cprev = cs[p];
            float cnew = fg * cprev + ig * ng;
            float hnew = og * tanhf(cnew);
            cs[p] = cnew;
            outt[(size_t)b * HH + u] = hnew;

            // next-step B fragment write (single fp16)
            int kt = u >> 4, kk = u & 15, nt = b >> 3;
            int lt = ((b & 7) << 2) | ((kk >> 1) & 3);
            int rg = kk >> 3, hf = kk & 1;
            size_t wi = ((size_t)(kt * 8 + nt) * 32 + lt) * 2 + rg;
            ((__half*)&g_hfrag[nb][wi])[hf] = __float2half_rn(hnew);

            if (t == TT - 1 && full) {
                hfin[(size_t)b * HH + u] = hnew;
                cfin[(size_t)b * HH + u] = cnew;
            }
        }

        // grid barrier
        __threadfence();
        __syncthreads();
        if (tid == 0) {
            int v = atomicAdd(&g_arrive, 1);
            if (v == NCTA * (t + 1) - 1) atomicExch(&g_gen, t + 1);
            volatile int* vg = &g_gen;
            while (*vg < t + 1) __nanosleep(32);
        }
        __syncthreads();
    }
}

// ---------------------------------------------------------------------------
extern "C" void kernel_launch(void* const* d_in, const int* in_sizes, int n_in,
                              void* d_out, int out_size)
{
    const float* input_ = (const float*)d_in[0];
    const float* h0     = (const float*)d_in[1];
    const float* c0     = (const float*)d_in[2];
    const float* Wx     = (const float*)d_in[3];
    const float* Wh     = (const float*)d_in[4];
    const float* bx     = (const float*)d_in[5];
    const float* bh     = (const float*)d_in[6];
    float* out = (float*)d_out;
    (void)in_sizes; (void)n_in;

    cudaFuncSetAttribute(lstm_persist, cudaFuncAttributeMaxDynamicSharedMemorySize, SM_TOTAL);

    reset_bar<<<1, 1>>>();
    pack_whp<<<(G4 * HH) / 256, 256>>>(Wh);
    pack_wx<<<(G4 * II) / 256, 256>>>(Wx);
    pack_x<<<(int)(((size_t)TT * BB * II) / 256), 256>>>(input_);
    pack_h0<<<(BB * HH) / 256, 256>>>(h0);

    dim3 ggrid(G4 / 128, (TT * BB) / 128);
    gx_mma_kernel<<<ggrid, 256>>>(bx, bh);

    long long need = (long long)TT * BB * HH + 2LL * BB * HH;
    int full = (out_size >= need) ? 1 : 0;
    float* hfin = out + (size_t)TT * BB * HH;
    float* cfin = hfin + (size_t)BB * HH;

    lstm_persist<<<NCTA, 256, SM_TOTAL>>>(c0, out, hfin, cfin, full);
}

// round 6
// speedup vs baseline: 8.9715x; 1.3226x over previous
#include <cuda_runtime.h>
#include <cuda_fp16.h>
#include <math.h>
#include <stdint.h>

#define TT 512
#define BB 64
#define II 1024
#define HH 1024
#define G4 4096
#define NCTA 128

// ---------------- device scratch (static, no runtime alloc) ----------------
static __device__ float g_gx[(size_t)TT * BB * G4];        // fp32: X@Wx^T + bx + bh
// Wh fp16 (single), per-CTA blob: [c128][mt2][kt64][lane32][reg4]
static __device__ uint32_t g_whp[(size_t)NCTA * 16384];
// Wx fp16 (single): [nt512][kt64][lane32][reg2]
static __device__ uint32_t g_wxfrag[(size_t)512 * 64 * 64];
// X fp16: [mt2048][kt64][lane32][reg4]
static __device__ uint32_t g_xfrag[(size_t)2048 * 64 * 128];
// h fp16 (double buffered): [buf2][kt64][nt8][lane32][reg2]
static __device__ uint32_t g_hfrag[2][64 * 8 * 64];
static __device__ int g_arrive;
static __device__ int g_gen;

// ---------------- mma.sync m16n8k16 fp16 (base sm_80+) ----------------
__device__ __forceinline__ void mma16816(float* c, const uint32_t* a, const uint32_t* b) {
    asm volatile(
        "mma.sync.aligned.m16n8k16.row.col.f32.f16.f16.f32 "
        "{%0,%1,%2,%3}, {%4,%5,%6,%7}, {%8,%9}, {%0,%1,%2,%3};"
        : "+f"(c[0]), "+f"(c[1]), "+f"(c[2]), "+f"(c[3])
        : "r"(a[0]), "r"(a[1]), "r"(a[2]), "r"(a[3]), "r"(b[0]), "r"(b[1]));
}

// ---------------------------------------------------------------------------
// Pack kernels. Fragment layouts (validated R3-R5):
// A (16x16): lane=((r&7)<<2)|((kk>>1)&3), reg=((kk>>3)<<1)|(r>>3), half=kk&1
// B (8x16):  lane=((n&7)<<2)|((kk>>1)&3), reg=kk>>3,               half=kk&1
// ---------------------------------------------------------------------------
__global__ __launch_bounds__(256) void pack_whp(const float* __restrict__ Wh) {
    int idx = blockIdx.x * 256 + threadIdx.x;   // 4096*1024
    int row = idx >> 10, k = idx & 1023;
    int g = row >> 10, u = row & 1023;
    int c = u >> 3, ul = u & 7;
    int rm = g * 8 + ul;
    int mt = rm >> 4, r = rm & 15;
    int kt = k >> 4, kk = k & 15;
    int lane = ((r & 7) << 2) | ((kk >> 1) & 3);
    int reg = ((kk >> 3) << 1) | (r >> 3);
    int half = kk & 1;
    size_t base = (size_t)c * 16384 + ((size_t)mt * 64 + kt) * 128 + lane * 4 + reg;
    ((__half*)&g_whp[base])[half] = __float2half_rn(Wh[idx]);
}

__global__ __launch_bounds__(256) void pack_wx(const float* __restrict__ Wx) {
    int idx = blockIdx.x * 256 + threadIdx.x;   // 4096*1024
    int n = idx >> 10, k = idx & 1023;
    int nt = n >> 3, nl = n & 7;
    int kt = k >> 4, kk = k & 15;
    int lane = (nl << 2) | ((kk >> 1) & 3);
    int reg = kk >> 3;
    int half = kk & 1;
    size_t wi = ((size_t)(nt * 64 + kt) * 32 + lane) * 2 + reg;
    ((__half*)&g_wxfrag[wi])[half] = __float2half_rn(Wx[idx]);
}

__global__ __launch_bounds__(256) void pack_x(const float* __restrict__ X) {
    size_t idx = (size_t)blockIdx.x * 256 + threadIdx.x;  // 32768*1024
    int row = (int)(idx >> 10), k = (int)(idx & 1023);
    int mt = row >> 4, r = row & 15;
    int kt = k >> 4, kk = k & 15;
    int lane = ((r & 7) << 2) | ((kk >> 1) & 3);
    int reg = ((kk >> 3) << 1) | (r >> 3);
    int half = kk & 1;
    size_t wi = (((size_t)mt * 64 + kt) * 32 + lane) * 4 + reg;
    ((__half*)&g_xfrag[wi])[half] = __float2half_rn(X[idx]);
}

__global__ __launch_bounds__(256) void pack_h0(const float* __restrict__ h0) {
    int idx = blockIdx.x * 256 + threadIdx.x;   // 64*1024
    int b = idx >> 10, u = idx & 1023;
    int kt = u >> 4, kk = u & 15;
    int nt = b >> 3;
    int lane = ((b & 7) << 2) | ((kk >> 1) & 3);
    int reg = kk >> 3;
    int half = kk & 1;
    size_t wi = ((size_t)(kt * 8 + nt) * 32 + lane) * 2 + reg;
    ((__half*)&g_hfrag[0][wi])[half] = __float2half_rn(h0[idx]);
}

__global__ void reset_bar() { g_arrive = 0; g_gen = 0; }

// ---------------------------------------------------------------------------
// gx GEMM (tensor): gx = X@Wx^T + bx + bh. Single fp16 product.
// grid (32, 256); 8 warps: 4 mtiles x 4 ntiles each; 16 MMA per kt per warp.
// ---------------------------------------------------------------------------
__global__ __launch_bounds__(256) void gx_mma_kernel(
    const float* __restrict__ bx, const float* __restrict__ bh)
{
    const int tid = threadIdx.x;
    const int wid = tid >> 5, lane = tid & 31;
    const int wm = wid & 1, wn = wid >> 1;
    const int mtb = blockIdx.y * 8 + wm * 4;
    const int ntb = blockIdx.x * 16 + wn * 4;

    float acc[4][4][4];
#pragma unroll
    for (int i = 0; i < 4; i++)
#pragma unroll
        for (int j = 0; j < 4; j++)
#pragma unroll
            for (int q = 0; q < 4; q++) acc[i][j][q] = 0.f;

    const uint32_t* Af = g_xfrag + (size_t)lane * 4;
    const uint32_t* Bf = g_wxfrag + (size_t)lane * 2;

#pragma unroll 2
    for (int kt = 0; kt < 64; kt++) {
        uint32_t b_f[4][2];
#pragma unroll
        for (int nt = 0; nt < 4; nt++) {
            size_t bo = (size_t)((ntb + nt) * 64 + kt) * 64;
            *(uint2*)b_f[nt] = *(const uint2*)(Bf + bo);
        }
#pragma unroll
        for (int mt = 0; mt < 4; mt++) {
            size_t ao = ((size_t)(mtb + mt) * 64 + kt) * 128;
            uint32_t a[4];
            *(uint4*)a = *(const uint4*)(Af + ao);
#pragma unroll
            for (int nt = 0; nt < 4; nt++)
                mma16816(acc[mt][nt], a, b_f[nt]);
        }
    }

#pragma unroll
    for (int mt = 0; mt < 4; mt++) {
        int row = (mtb + mt) * 16 + (lane >> 2);
#pragma unroll
        for (int nt = 0; nt < 4; nt++) {
            int col = (ntb + nt) * 8 + (lane & 3) * 2;
            float bb0 = bx[col] + bh[col];
            float bb1 = bx[col + 1] + bh[col + 1];
            float2 v0 = make_float2(acc[mt][nt][0] + bb0, acc[mt][nt][1] + bb1);
            float2 v1 = make_float2(acc[mt][nt][2] + bb0, acc[mt][nt][3] + bb1);
            *(float2*)(g_gx + (size_t)row * G4 + col) = v0;
            *(float2*)(g_gx + (size_t)(row + 8) * G4 + col) = v1;
        }
    }
}

// ---------------------------------------------------------------------------
// Persistent recurrence: 128 CTAs x 256 threads, 512 steps in one launch.
// CTA c owns cells [c*8, c*8+8). Warp w: mt = w>>2, K-quarter q = w&3.
// Wh fp16 resident in SMEM (64KB); h fp16 frags via L2; grid barrier.
// ---------------------------------------------------------------------------
#define GS_OFF   65536
#define CS_OFF   (GS_OFF + 4 * 32 * 68 * 4)
#define SM_TOTAL (CS_OFF + 2048)

__global__ __launch_bounds__(256, 1) void lstm_persist(
    const float* __restrict__ c0,
    float* __restrict__ out,
    float* __restrict__ hfin, float* __restrict__ cfin,
    int full)
{
    extern __shared__ __align__(16) char sm[];
    uint32_t (*whs)[64][128] = (uint32_t (*)[64][128])sm;   // [mt][kt][lane*4+reg]
    float (*Gs)[32][68] = (float (*)[32][68])(sm + GS_OFF);
    float* cs = (float*)(sm + CS_OFF);

    const int cta = blockIdx.x;
    const int tid = threadIdx.x;
    const int wid = tid >> 5, lane = tid & 31;
    const int mt = wid >> 2, q = wid & 3;

    {
        const uint4* src = (const uint4*)(g_whp + (size_t)cta * 16384);
        uint4* dst = (uint4*)sm;
        for (int i = tid; i < 4096; i += 256) dst[i] = src[i];
        for (int i = tid; i < 512; i += 256) {
            int b = i >> 3, ul = i & 7;
            cs[i] = c0[(size_t)b * HH + cta * 8 + ul];
        }
    }
    __syncthreads();

    for (int t = 0; t < TT; t++) {
        const uint32_t* Bf = &g_hfrag[t & 1][0];

        // prefetch gx epilogue values early (hidden under MMA)
        float gpre[2][4];
#pragma unroll
        for (int pp = 0; pp < 2; pp++) {
            const int p = tid + pp * 256;
            const int b = p >> 3, ul = p & 7;
            const float* gxr = g_gx + ((size_t)t * BB + b) * G4 + cta * 8 + ul;
#pragma unroll
            for (int g = 0; g < 4; g++) gpre[pp][g] = __ldcg(gxr + g * HH);
        }

        float acc[8][4];
#pragma unroll
        for (int i = 0; i < 8; i++)
#pragma unroll
            for (int j = 0; j < 4; j++) acc[i][j] = 0.f;

        const int kt0 = q * 16;
#pragma unroll 4
        for (int kt = kt0; kt < kt0 + 16; kt++) {
            uint4 a_v = *(const uint4*)&whs[mt][kt][lane * 4];
            const uint32_t* a = (const uint32_t*)&a_v;
            uint2 bf[8];
#pragma unroll
            for (int nt = 0; nt < 8; nt++) {
                uint32_t off = (uint32_t)(kt * 8 + nt) * 64 + lane * 2;
                bf[nt] = __ldcg((const uint2*)(Bf + off));
            }
#pragma unroll
            for (int nt = 0; nt < 8; nt++) mma16816(acc[nt], a, (const uint32_t*)&bf[nt]);
        }

        // scatter partials: Gs[q][row32][b]
        {
            const int r0 = mt * 16 + (lane >> 2);
#pragma unroll
            for (int nt = 0; nt < 8; nt++) {
                int col = nt * 8 + (lane & 3) * 2;
                Gs[q][r0][col]     = acc[nt][0];
                Gs[q][r0][col + 1] = acc[nt][1];
                Gs[q][r0 + 8][col]     = acc[nt][2];
                Gs[q][r0 + 8][col + 1] = acc[nt][3];
            }
        }
        __syncthreads();

        // cell update: 2 cells per thread
        float* outt = out + (size_t)t * BB * HH;
        const int nb = (t + 1) & 1;
        float hsave[2], csave[2];
#pragma unroll
        for (int pp = 0; pp < 2; pp++) {
            const int p = tid + pp * 256;
            const int b = p >> 3, ul = p & 7;
            const int u = cta * 8 + ul;

            float x0 = Gs[0][ul][b] + Gs[1][ul][b] + Gs[2][ul][b] + Gs[3][ul][b] + gpre[pp][0];
            float x1 = Gs[0][8 + ul][b] + Gs[1][8 + ul][b] + Gs[2][8 + ul][b] + Gs[3][8 + ul][b] + gpre[pp][1];
            float x2 = Gs[0][16 + ul][b] + Gs[1][16 + ul][b] + Gs[2][16 + ul][b] + Gs[3][16 + ul][b] + gpre[pp][2];
            float x3 = Gs[0][24 + ul][b] + Gs[1][24 + ul][b] + Gs[2][24 + ul][b] + Gs[3][24 + ul][b] + gpre[pp][3];

            float ig = 1.f / (1.f + __expf(-x0));
            float fg = 1.f / (1.f + __expf(-x1));
            float og = 1.f / (1.f + __expf(-x2));
            float ng = tanhf(x3);

            float cprev = cs[p];
            float cnew = fg * cprev + ig * ng;
            float hnew = og * tanhf(cnew);
            cs[p] = cnew;
            hsave[pp] = hnew;
            csave[pp] = cnew;

            // next-step B fragment write (fp16) — on the critical path
            int kt = u >> 4, kk = u & 15, nt = b >> 3;
            int lt = ((b & 7) << 2) | ((kk >> 1) & 3);
            int rg = kk >> 3, hf = kk & 1;
            size_t wi = ((size_t)(kt * 8 + nt) * 32 + lt) * 2 + rg;
            ((__half*)&g_hfrag[nb][wi])[hf] = __float2half_rn(hnew);
        }

        // barrier arrive as early as possible (h frags published)
        __threadfence();
        __syncthreads();
        if (tid == 0) atomicAdd(&g_arrive, 1);

        // off-critical-path stores: outputs (nobody reads these this pass)
#pragma unroll
        for (int pp = 0; pp < 2; pp++) {
            const int p = tid + pp * 256;
            const int b = p >> 3, ul = p & 7;
            const int u = cta * 8 + ul;
            outt[(size_t)b * HH + u] = hsave[pp];
            if (t == TT - 1 && full) {
                hfin[(size_t)b * HH + u] = hsave[pp];
                cfin[(size_t)b * HH + u] = csave[pp];
            }
        }

        // barrier wait
        if (tid == 0) {
            volatile int* va = &g_arrive;
            while (*va < NCTA * (t + 1)) __nanosleep(32);
        }
        __syncthreads();
    }
}

// ---------------------------------------------------------------------------
extern "C" void kernel_launch(void* const* d_in, const int* in_sizes, int n_in,
                              void* d_out, int out_size)
{
    const float* input_ = (const float*)d_in[0];
    const float* h0     = (const float*)d_in[1];
    const float* c0     = (const float*)d_in[2];
    const float* Wx     = (const float*)d_in[3];
    const float* Wh     = (const float*)d_in[4];
    const float* bx     = (const float*)d_in[5];
    const float* bh     = (const float*)d_in[6];
    float* out = (float*)d_out;
    (void)in_sizes; (void)n_in;

    cudaFuncSetAttribute(lstm_persist, cudaFuncAttributeMaxDynamicSharedMemorySize, SM_TOTAL);

    reset_bar<<<1, 1>>>();
    pack_whp<<<(G4 * HH) / 256, 256>>>(Wh);
    pack_wx<<<(G4 * II) / 256, 256>>>(Wx);
    pack_x<<<(int)(((size_t)TT * BB * II) / 256), 256>>>(input_);
    pack_h0<<<(BB * HH) / 256, 256>>>(h0);

    dim3 ggrid(G4 / 128, (TT * BB) / 128);
    gx_mma_kernel<<<ggrid, 256>>>(bx, bh);

    long long need = (long long)TT * BB * HH + 2LL * BB * HH;
    int full = (out_size >= need) ? 1 : 0;
    float* hfin = out + (size_t)TT * BB * HH;
    float* cfin = hfin + (size_t)BB * HH;

    lstm_persist<<<NCTA, 256, SM_TOTAL>>>(c0, out, hfin, cfin, full);
}